// round 8
// baseline (speedup 1.0000x reference)
#include <cuda_runtime.h>
#include <cstdint>

#define NB 16
#define NC 64
#define NT 2048
#define KNN 3
#define NTILE 16      // NT/128
#define NPAIR 136     // NTILE*(NTILE+1)/2

// scratch (static __device__ arrays: allocation-free per harness rules)
__device__ float g_nsq[NB * NT];
__device__ float g_cs[(size_t)NB * NT * NTILE * KNN];  // candidate scores
__device__ int   g_ci[(size_t)NB * NT * NTILE * KNN];  // candidate indices

// ---------------- tf32 mma helpers (portable sm_80+ PTX; no 'a' feature) -----------
__device__ __forceinline__ uint32_t f2tf(float f) {
    uint32_t r; asm("cvt.rna.tf32.f32 %0, %1;" : "=r"(r) : "f"(f)); return r;
}
__device__ __forceinline__ void mma_tf32(float* c, uint32_t a0, uint32_t a1, uint32_t a2,
                                         uint32_t a3, uint32_t b0, uint32_t b1) {
    asm volatile("mma.sync.aligned.m16n8k8.row.col.f32.tf32.tf32.f32 "
        "{%0,%1,%2,%3}, {%4,%5,%6,%7}, {%8,%9}, {%0,%1,%2,%3};"
        : "+f"(c[0]), "+f"(c[1]), "+f"(c[2]), "+f"(c[3])
        : "r"(a0), "r"(a1), "r"(a2), "r"(a3), "r"(b0), "r"(b1));
}

// top-3 insert with (score, index) lexicographic tie-break (== lax.top_k stability)
#define INS3(SC, SI)                                                          \
    do {                                                                      \
        float _s = (SC); int _i = (SI);                                       \
        if (_s < q2 || (_s == q2 && _i < j2)) {                               \
            q2 = _s; j2 = _i;                                                 \
            if (q2 < q1 || (q2 == q1 && j2 < j1)) {                           \
                float _t = q1; q1 = q2; q2 = _t;                              \
                int _k = j1; j1 = j2; j2 = _k;                                \
                if (q1 < q0 || (q1 == q0 && j1 < j0)) {                       \
                    _t = q0; q0 = q1; q1 = _t;                                \
                    _k = j0; j0 = j1; j1 = _k;                                \
                }                                                             \
            }                                                                 \
        }                                                                     \
    } while (0)

// ---------------- kernel 1: squared norms ------------------------------------------
__global__ void nsq_kernel(const float* __restrict__ x) {
    int gid = blockIdx.x * blockDim.x + threadIdx.x;   // 2*NB*NT threads
    int half = gid & 1;
    int t = (gid >> 1) & (NT - 1);
    int b = gid >> 12;
    const float* xp = x + ((size_t)(b * NC + half * 32)) * NT + t;
    float s = 0.f;
#pragma unroll
    for (int c = 0; c < 32; c++) {
        float v = xp[(size_t)c * NT];
        s = fmaf(v, v, s);
    }
    s += __shfl_xor_sync(0xffffffffu, s, 1);
    if (!half) g_nsq[b * NT + t] = s;
}

// ---------------- kernel 2: tf32-split tensor gram + bidirectional top-3 -----------
// One block per (ti, tj) pair, tj >= ti. x tiles staged to smem [64][136]; MMA
// fragments loaded DIRECTLY via scalar LDS (pad-136 makes the fragment address
// pattern a perfect bank permutation) with in-register tf32 hi/lo split.
// 3-term split GEMM (hh + hl + lh) via mma.m16n8k8. C dumped to pad-132 score
// buffer (overlay), then concurrent row-side / column-side top-3 scans.
extern __shared__ float smem[];

// float offsets within dynamic smem
#define SM_XA   0          // [64][136] staged x tile (rows=c=k, cols=t)
#define SM_XB   8704
#define SM_NSQR 17408
#define SM_NSQC 17536
#define GRAM_SMEM_BYTES (17664 * 4)   // 70656 B -> 3 blocks/SM
// score buffer overlays XA/XB after MMA: [128][132] = 16896 floats < 17408

__global__ __launch_bounds__(256) void gram_tc_kernel(const float* __restrict__ x) {
    const int tid  = threadIdx.x;
    const int wid  = tid >> 5;
    const int lane = tid & 31;
    const int b = blockIdx.y;

    // closed-form upper-triangle decode: p -> (ti, tj), tj >= ti
    const int p = blockIdx.x;
    int ti = (int)(NTILE + 0.5f - sqrtf((NTILE + 0.5f) * (NTILE + 0.5f) - 2.0f * p));
    int off = ti * NTILE - (ti * (ti - 1)) / 2;
    if (p < off)                    { ti--; off = ti * NTILE - (ti * (ti - 1)) / 2; }
    else if (p >= off + NTILE - ti) { ti++; off = ti * NTILE - (ti * (ti - 1)) / 2; }
    const int tj = ti + (p - off);
    const int t0 = ti * 128, s0 = tj * 128;
    const bool diag = (ti == tj);

    const float4* xb4 = (const float4*)(x + (size_t)b * NC * NT);

    // ---- phase 1: coalesced stage of x tiles into [c][136] smem ----
    for (int i = tid; i < 2048; i += 256) {             // 2048 float4 per tile
        int c = i >> 5, t4 = i & 31;
        *(float4*)&smem[SM_XA + c * 136 + 4 * t4] = xb4[c * (NT / 4) + (t0 >> 2) + t4];
    }
    if (!diag) {
        for (int i = tid; i < 2048; i += 256) {
            int c = i >> 5, t4 = i & 31;
            *(float4*)&smem[SM_XB + c * 136 + 4 * t4] = xb4[c * (NT / 4) + (s0 >> 2) + t4];
        }
    }
    if (tid < 128) smem[SM_NSQR + tid] = g_nsq[b * NT + t0 + tid];
    else           smem[SM_NSQC + tid - 128] = g_nsq[b * NT + s0 + tid - 128];
    __syncthreads();

    // ---- phase 2: 3-term tf32 MMA, fragments straight from XA/XB ----
    // warp tile 64(m) x 32(n); A frag rows r=lane/4(+8), k=ks*8+lane%4(+4)
    const int wm = wid & 1, wn = wid >> 1;
    const float* XA = smem + SM_XA;
    const float* XB = diag ? (smem + SM_XA) : (smem + SM_XB);

    float c[4][4][4];
#pragma unroll
    for (int i = 0; i < 4; i++)
#pragma unroll
        for (int j = 0; j < 4; j++)
#pragma unroll
            for (int e = 0; e < 4; e++) c[i][j][e] = 0.f;

#pragma unroll
    for (int ks = 0; ks < 8; ks++) {
        const int k0 = ks * 8 + (lane & 3);
        uint32_t ah[4][4], al[4][4];
#pragma unroll
        for (int i = 0; i < 4; i++) {
            int r = wm * 64 + i * 16 + (lane >> 2);
            float f0 = XA[k0 * 136 + r];
            float f1 = XA[k0 * 136 + r + 8];
            float f2 = XA[(k0 + 4) * 136 + r];
            float f3 = XA[(k0 + 4) * 136 + r + 8];
            ah[i][0] = f2tf(f0); al[i][0] = f2tf(f0 - __uint_as_float(ah[i][0]));
            ah[i][1] = f2tf(f1); al[i][1] = f2tf(f1 - __uint_as_float(ah[i][1]));
            ah[i][2] = f2tf(f2); al[i][2] = f2tf(f2 - __uint_as_float(ah[i][2]));
            ah[i][3] = f2tf(f3); al[i][3] = f2tf(f3 - __uint_as_float(ah[i][3]));
        }
#pragma unroll
        for (int j = 0; j < 4; j++) {
            int n = wn * 32 + j * 8 + (lane >> 2);
            float g0 = XB[k0 * 136 + n];
            float g1 = XB[(k0 + 4) * 136 + n];
            uint32_t bh0 = f2tf(g0), bl0 = f2tf(g0 - __uint_as_float(bh0));
            uint32_t bh1 = f2tf(g1), bl1 = f2tf(g1 - __uint_as_float(bh1));
#pragma unroll
            for (int i = 0; i < 4; i++) {
                mma_tf32(c[i][j], ah[i][0], ah[i][1], ah[i][2], ah[i][3], bh0, bh1);
                mma_tf32(c[i][j], ah[i][0], ah[i][1], ah[i][2], ah[i][3], bl0, bl1);
                mma_tf32(c[i][j], al[i][0], al[i][1], al[i][2], al[i][3], bh0, bh1);
            }
        }
    }
    __syncthreads();   // tile reads done; score may overlay XA/XB

    // ---- dump C to score[128][132] (overlay) ----
    float* score = smem;   // [128][132]
#pragma unroll
    for (int i = 0; i < 4; i++) {
        int m = wm * 64 + i * 16 + (lane >> 2);
#pragma unroll
        for (int j = 0; j < 4; j++) {
            int n = wn * 32 + j * 8 + 2 * (lane & 3);
            *(float2*)&score[m * 132 + n]       = make_float2(c[i][j][0], c[i][j][1]);
            *(float2*)&score[(m + 8) * 132 + n] = make_float2(c[i][j][2], c[i][j][3]);
        }
    }
    __syncthreads();

    float* nsqR = smem + SM_NSQR;
    float* nsqC = smem + SM_NSQC;

    // row-side (warps 0-3) and column-side (warps 4-7) scans run concurrently
    if (tid < 128) {
        float q0 = 3.4e38f, q1 = 3.4e38f, q2 = 3.4e38f;
        int   j0 = 0x7fffffff, j1 = 0x7fffffff, j2 = 0x7fffffff;
        const float* rowp = &score[tid * 132];
        for (int i = 0; i < 128; i++) {
            int jj = (i + tid) & 127;                   // skew: conflict-free (pad 132)
            float sc = fmaf(-2.f, rowp[jj], nsqC[jj]);
            INS3(sc, s0 + jj);
        }
        size_t base = ((size_t)(b * NT + t0 + tid) * NTILE + tj) * KNN;
        g_cs[base + 0] = q0; g_ci[base + 0] = j0;
        g_cs[base + 1] = q1; g_ci[base + 1] = j1;
        g_cs[base + 2] = q2; g_ci[base + 2] = j2;
    } else if (!diag) {
        int cc = tid - 128;
        float q0 = 3.4e38f, q1 = 3.4e38f, q2 = 3.4e38f;
        int   j0 = 0x7fffffff, j1 = 0x7fffffff, j2 = 0x7fffffff;
        for (int i = 0; i < 128; i++) {
            int jj = (i + cc) & 127;
            float sc = fmaf(-2.f, score[jj * 132 + cc], nsqR[jj]);
            INS3(sc, t0 + jj);
        }
        size_t base = ((size_t)(b * NT + s0 + cc) * NTILE + ti) * KNN;
        g_cs[base + 0] = q0; g_ci[base + 0] = j0;
        g_cs[base + 1] = q1; g_ci[base + 1] = j1;
        g_cs[base + 2] = q2; g_ci[base + 2] = j2;
    }
}

// ---------------- kernel 3: candidate merge + gather + conv ------------------------
// out[b,o,t] = bias[o] + sum_j W[o*192+j] * x[b, j/3, idx[b,t,j%3]]
__global__ __launch_bounds__(256) void conv_kernel(const float* __restrict__ x,
                                                   const float* __restrict__ W,
                                                   const float* __restrict__ bias,
                                                   float* __restrict__ out) {
    const int b  = blockIdx.y;
    const int t0 = blockIdx.x * 128;
    float* Ws   = smem;                                 // [192][64] transposed
    float* ps   = smem + 192 * 64;                      // [64][128] gathered chunk
    int*   sidx = (int*)(smem + 192 * 64 + 64 * 128);   // [128*3]

    const int tid = threadIdx.x;
    for (int i = tid; i < 192 * 64; i += 256) {
        int j = i >> 6, o = i & 63;
        Ws[i] = W[o * 192 + j];
    }
    // merge this block's 128 rows: 16 slots x 3 candidates -> final top-3
    if (tid < 128) {
        size_t cb = (size_t)(b * NT + t0 + tid) * (NTILE * KNN);
        float q0 = 3.4e38f, q1 = 3.4e38f, q2 = 3.4e38f;
        int   j0 = 0x7fffffff, j1 = 0x7fffffff, j2 = 0x7fffffff;
#pragma unroll 8
        for (int e = 0; e < NTILE * KNN; e++) {
            float sc = g_cs[cb + e];
            int   si = g_ci[cb + e];
            INS3(sc, si);
        }
        sidx[tid * KNN + 0] = j0;
        sidx[tid * KNN + 1] = j1;
        sidx[tid * KNN + 2] = j2;
    }

    const int to = tid & 15;   // o-group: o = to*4 .. +3
    const int tt = tid >> 4;   // t-group: t = tt*8 .. +7
    float acc[4][8];
#pragma unroll
    for (int r = 0; r < 4; r++)
#pragma unroll
        for (int e = 0; e < 8; e++) acc[r][e] = 0.f;

    const float* xb = x + (size_t)b * NC * NT;

    for (int jc = 0; jc < 3; jc++) {
        __syncthreads();  // Ws/sidx ready (first), ps free (later)
        for (int i = tid; i < 64 * 128; i += 256) {
            int jj = i >> 7, tl = i & 127;
            int j  = jc * 64 + jj;
            int ch = j / 3;
            int kk = j - ch * 3;
            ps[i] = xb[(size_t)ch * NT + sidx[tl * KNN + kk]];  // L2-resident gather
        }
        __syncthreads();
#pragma unroll 8
        for (int jj = 0; jj < 64; jj++) {
            float4 w4 = *(const float4*)&Ws[(jc * 64 + jj) * 64 + to * 4];
            float4 p0 = *(const float4*)&ps[jj * 128 + tt * 8];
            float4 p1 = *(const float4*)&ps[jj * 128 + tt * 8 + 4];
            float pv[8] = {p0.x, p0.y, p0.z, p0.w, p1.x, p1.y, p1.z, p1.w};
            float wv[4] = {w4.x, w4.y, w4.z, w4.w};
#pragma unroll
            for (int r = 0; r < 4; r++)
#pragma unroll
                for (int e = 0; e < 8; e++)
                    acc[r][e] = fmaf(wv[r], pv[e], acc[r][e]);
        }
    }

#pragma unroll
    for (int r = 0; r < 4; r++) {
        int o = to * 4 + r;
        float bo = __ldg(&bias[o]);
        float* op = out + ((size_t)(b * NC + o)) * NT + t0 + tt * 8;
#pragma unroll
        for (int e = 0; e < 8; e++) op[e] = acc[r][e] + bo;
    }
}

// ---------------- launch -----------------------------------------------------------
extern "C" void kernel_launch(void* const* d_in, const int* in_sizes, int n_in,
                              void* d_out, int out_size) {
    const float* x    = (const float*)d_in[0];
    const float* W    = (const float*)d_in[1];
    const float* bias = (const float*)d_in[2];
    float* out        = (float*)d_out;

    const int conv_smem = (192 * 64 + 64 * 128 + 128 * KNN) * 4;          // 83456 B
    cudaFuncSetAttribute(gram_tc_kernel, cudaFuncAttributeMaxDynamicSharedMemorySize, GRAM_SMEM_BYTES);
    cudaFuncSetAttribute(conv_kernel, cudaFuncAttributeMaxDynamicSharedMemorySize, conv_smem);

    nsq_kernel<<<(2 * NB * NT) / 256, 256>>>(x);
    gram_tc_kernel<<<dim3(NPAIR, NB), 256, GRAM_SMEM_BYTES>>>(x);
    conv_kernel<<<dim3(NT / 128, NB), 256, conv_smem>>>(x, W, bias, out);
}